// round 4
// baseline (speedup 1.0000x reference)
#include <cuda_runtime.h>
#include <cuda_bf16.h>

#define EPS 1e-5f

typedef unsigned long long u64;

// ---------------- f32x2 packed helpers (sm_103a) ----------------
__device__ __forceinline__ u64 pk2(float lo, float hi) {
    u64 r;
    asm("mov.b64 %0, {%1, %2};" : "=l"(r) : "f"(lo), "f"(hi));
    return r;
}
__device__ __forceinline__ void upk2(u64 v, float& lo, float& hi) {
    asm("mov.b64 {%0, %1}, %2;" : "=f"(lo), "=f"(hi) : "l"(v));
}
__device__ __forceinline__ u64 ffma2_(u64 a, u64 b, u64 c) {
    u64 d;
    asm("fma.rn.f32x2 %0, %1, %2, %3;" : "=l"(d) : "l"(a), "l"(b), "l"(c));
    return d;
}
__device__ __forceinline__ u64 fmul2_(u64 a, u64 b) {
    u64 d;
    asm("mul.rn.f32x2 %0, %1, %2;" : "=l"(d) : "l"(a), "l"(b));
    return d;
}

// ---------------- cp.async helpers ----------------
__device__ __forceinline__ void cp16(void* smem_dst, const void* gsrc) {
    unsigned s = (unsigned)__cvta_generic_to_shared(smem_dst);
    asm volatile("cp.async.cg.shared.global [%0], [%1], 16;" :: "r"(s), "l"(gsrc));
}
__device__ __forceinline__ void cp_commit() {
    asm volatile("cp.async.commit_group;");
}
template <int N>
__device__ __forceinline__ void cp_wait() {
    asm volatile("cp.async.wait_group %0;" :: "n"(N));
}

// ---------------- scratch ----------------
__device__ float  g_x_nhwc[4 * 64 * 64 * 256];   // [b][h][w][c]
__device__ int4   g_off4[4 * 9 * 64 * 64];       // clamped corner elem offsets
__device__ float4 g_cw[4 * 9 * 64 * 64];         // corner weights (0 if invalid)
__device__ float2 g_pwT2[256 * 256];             // [c][o] = (w,w) duplicated, w = pw[o][c]*bn_scale
__device__ float  g_bias[256];
__device__ float  g_midT[256 * 16384];           // [c][p], p = b*4096 + h*64 + w

// ---------------- kernel 1: NCHW -> NHWC transpose ----------------
__global__ void k_transpose(const float* __restrict__ x) {
    __shared__ float tile[32][33];
    int b  = blockIdx.z;
    int s0 = blockIdx.x * 32;
    int c0 = blockIdx.y * 32;
    int tx = threadIdx.x, ty = threadIdx.y;  // (32, 8)
    const float* xb = x + (size_t)b * 256 * 4096;
    float* ob = g_x_nhwc + (size_t)b * 4096 * 256;
#pragma unroll
    for (int i = 0; i < 32; i += 8)
        tile[ty + i][tx] = xb[(c0 + ty + i) * 4096 + s0 + tx];
    __syncthreads();
#pragma unroll
    for (int i = 0; i < 32; i += 8)
        ob[(s0 + ty + i) * 256 + c0 + tx] = tile[tx][ty + i];
}

// ---------------- kernel 2: weight prep ----------------
__global__ void k_prep(const float* __restrict__ pw, const float* __restrict__ bg,
                       const float* __restrict__ bb, const float* __restrict__ bm,
                       const float* __restrict__ bv) {
    int idx = blockIdx.x * 256 + threadIdx.x;   // 65536 total
    int o  = idx & 255;
    int cc = idx >> 8;
    float s = bg[o] * rsqrtf(bv[o] + EPS);
    float v = __ldg(pw + o * 256 + cc) * s;
    g_pwT2[cc * 256 + o] = make_float2(v, v);
    if (idx < 256) {
        float s2 = bg[idx] * rsqrtf(bv[idx] + EPS);
        g_bias[idx] = bb[idx] - bm[idx] * s2;
    }
}

// ---------------- kernel 3: offset conv + sampling params ----------------
__global__ void k_offset(const float* __restrict__ gf, const float* __restrict__ offw,
                         const float* __restrict__ og, const float* __restrict__ obt,
                         const float* __restrict__ om, const float* __restrict__ ov) {
    __shared__ __align__(16) float2 s_w2[9][64][10];
    int bh = blockIdx.x;
    int b = bh >> 6, h = bh & 63;
    int w = threadIdx.x;   // 0..63

    for (int i = w; i < 9 * 64 * 9; i += 64) {
        int t = i % 9;
        int g = (i / 9) & 63;
        int k = i / 576;
        float wdy = offw[(2 * k) * 576 + g * 9 + t];
        float wdx = offw[(2 * k + 1) * 576 + g * 9 + t];
        s_w2[k][g][t] = make_float2(wdy, wdx);
    }
    __syncthreads();

    u64 acc[9];
#pragma unroll
    for (int k = 0; k < 9; k++) acc[k] = 0ull;

    const float* gfb = gf + (size_t)b * 64 * 64 * 64;
    for (int g = 0; g < 64; g++) {
        float a[9];
#pragma unroll
        for (int r = 0; r < 3; r++) {
            int hh = h + r - 1;
            bool hv = (unsigned)hh < 64u;
#pragma unroll
            for (int q = 0; q < 3; q++) {
                int ww = w + q - 1;
                bool wv2 = (unsigned)ww < 64u;
                a[r * 3 + q] = (hv && wv2) ? __ldg(gfb + (g * 64 + hh) * 64 + ww) : 0.f;
            }
        }
        u64 a2[9];
#pragma unroll
        for (int t = 0; t < 9; t++) a2[t] = pk2(a[t], a[t]);
#pragma unroll
        for (int k = 0; k < 9; k++) {
            const u64* wr = (const u64*)&s_w2[k][g][0];
            ulonglong2 w01 = *(const ulonglong2*)(wr + 0);
            ulonglong2 w23 = *(const ulonglong2*)(wr + 2);
            ulonglong2 w45 = *(const ulonglong2*)(wr + 4);
            ulonglong2 w67 = *(const ulonglong2*)(wr + 6);
            u64 w8 = wr[8];
            acc[k] = ffma2_(w01.x, a2[0], acc[k]);
            acc[k] = ffma2_(w01.y, a2[1], acc[k]);
            acc[k] = ffma2_(w23.x, a2[2], acc[k]);
            acc[k] = ffma2_(w23.y, a2[3], acc[k]);
            acc[k] = ffma2_(w45.x, a2[4], acc[k]);
            acc[k] = ffma2_(w45.y, a2[5], acc[k]);
            acc[k] = ffma2_(w67.x, a2[6], acc[k]);
            acc[k] = ffma2_(w67.y, a2[7], acc[k]);
            acc[k] = ffma2_(w8,    a2[8], acc[k]);
        }
    }

#pragma unroll
    for (int k = 0; k < 9; k++) {
        float dyr, dxr;
        upk2(acc[k], dyr, dxr);
        int j0 = 2 * k, j1 = 2 * k + 1;
        float s0 = og[j0] * rsqrtf(ov[j0] + EPS);
        float s1 = og[j1] * rsqrtf(ov[j1] + EPS);
        float dy = fmaxf((dyr - om[j0]) * s0 + obt[j0], 0.f);
        float dx = fmaxf((dxr - om[j1]) * s1 + obt[j1], 0.f);
        float ky = (float)((k / 3) - 1) * 2.0f;   // DIL = 2
        float kx = (float)((k % 3) - 1) * 2.0f;
        float gy = (float)h + ky + dy;
        float gx = (float)w + kx + dx;
        float y0f = floorf(gy), x0f = floorf(gx);
        float wy = gy - y0f, wx = gx - x0f;
        float omwy = 1.f - wy, omwx = 1.f - wx;
        int y0 = (int)y0f, x0 = (int)x0f;
        bool yv0 = (unsigned)y0 < 64u;
        bool yv1 = (unsigned)(y0 + 1) < 64u;
        bool xv0 = (unsigned)x0 < 64u;
        bool xv1 = (unsigned)(x0 + 1) < 64u;
        int y0c = min(max(y0, 0), 63);
        int y1c = min(max(y0 + 1, 0), 63);
        int x0c = min(max(x0, 0), 63);
        int x1c = min(max(x0 + 1, 0), 63);
        int idx = ((b * 9 + k) * 64 + h) * 64 + w;
        g_off4[idx] = make_int4((y0c * 64 + x0c) * 256, (y0c * 64 + x1c) * 256,
                                (y1c * 64 + x0c) * 256, (y1c * 64 + x1c) * 256);
        g_cw[idx] = make_float4(omwy * omwx * (float)(yv0 && xv0),
                                omwy * wx   * (float)(yv0 && xv1),
                                wy * omwx   * (float)(yv1 && xv0),
                                wy * wx     * (float)(yv1 && xv1));
    }
}

// ---------------- kernel 4: sample + depthwise -> g_midT ----------------
__global__ __launch_bounds__(256, 3) void k_sample(const float* __restrict__ dw) {
    __shared__ float s_mid[16][264];                 // [p][c], padded
    __shared__ __align__(16) int4 s_off[9][16];
    __shared__ __align__(16) u64 s_cw[9][16][4];

    int t  = blockIdx.x;
    int w0 = (t & 3) << 4;
    int h  = (t >> 2) & 63;
    int b  = t >> 8;
    int tid = threadIdx.x;

    if (tid < 144) {
        int k = tid / 16, p = tid & 15;
        int idx = ((b * 9 + k) * 64 + h) * 64 + w0 + p;
        s_off[k][p] = g_off4[idx];
        float4 cw = g_cw[idx];
        s_cw[k][p][0] = pk2(cw.x, cw.x);
        s_cw[k][p][1] = pk2(cw.y, cw.y);
        s_cw[k][p][2] = pk2(cw.z, cw.z);
        s_cw[k][p][3] = pk2(cw.w, cw.w);
    }

    int cg = tid & 63;
    int c  = cg * 4;
    int ps = tid >> 6;

    u64 dwv[9][2];
#pragma unroll
    for (int k = 0; k < 9; k++) {
        dwv[k][0] = pk2(__ldg(dw + c * 9 + k),       __ldg(dw + (c + 1) * 9 + k));
        dwv[k][1] = pk2(__ldg(dw + (c + 2) * 9 + k), __ldg(dw + (c + 3) * 9 + k));
    }
    __syncthreads();

    const float* xb = g_x_nhwc + (size_t)b * 4096 * 256 + c;
#pragma unroll 2
    for (int i = 0; i < 4; i++) {
        int p = ps * 4 + i;
        u64 a0 = 0ull, a1 = 0ull;
#pragma unroll
        for (int k = 0; k < 9; k++) {
            int4 o4 = s_off[k][p];
            float4 v00 = __ldg((const float4*)(xb + o4.x));
            float4 v01 = __ldg((const float4*)(xb + o4.y));
            float4 v10 = __ldg((const float4*)(xb + o4.z));
            float4 v11 = __ldg((const float4*)(xb + o4.w));
            ulonglong2 c01 = *(const ulonglong2*)&s_cw[k][p][0];
            ulonglong2 c23 = *(const ulonglong2*)&s_cw[k][p][2];
            const u64* q00 = (const u64*)&v00;
            const u64* q01 = (const u64*)&v01;
            const u64* q10 = (const u64*)&v10;
            const u64* q11 = (const u64*)&v11;
            u64 b0 = fmul2_(c01.x, q00[0]);
            u64 b1 = fmul2_(c01.x, q00[1]);
            b0 = ffma2_(c01.y, q01[0], b0);
            b1 = ffma2_(c01.y, q01[1], b1);
            b0 = ffma2_(c23.x, q10[0], b0);
            b1 = ffma2_(c23.x, q10[1], b1);
            b0 = ffma2_(c23.y, q11[0], b0);
            b1 = ffma2_(c23.y, q11[1], b1);
            a0 = ffma2_(dwv[k][0], b0, a0);
            a1 = ffma2_(dwv[k][1], b1, a1);
        }
        float f0, f1, f2, f3;
        upk2(a0, f0, f1);
        upk2(a1, f2, f3);
        *(float4*)&s_mid[p][c] = make_float4(f0, f1, f2, f3);
    }
    __syncthreads();

    int p0 = b * 4096 + h * 64 + w0;
    for (int i2 = tid; i2 < 4096; i2 += 256) {
        int cc = i2 >> 4, pp = i2 & 15;
        g_midT[cc * 16384 + p0 + pp] = s_mid[pp][cc];
    }
}

// ---------------- kernel 5: pointwise GEMM + BN/ReLU ----------------
// C[256 o][16384 px]; block tile 64o x 256px; 256 threads; thread 8o x 8px.
// cp.async double-buffered loads; W pre-duplicated (w,w) pairs in global.
__global__ __launch_bounds__(256, 2) void k_gemm(float* __restrict__ out) {
    __shared__ __align__(16) u64  sW[2][8][64];
    __shared__ __align__(16) float sM[2][8][256];

    int tid  = threadIdx.x;
    int og   = tid >> 5;            // 0..7
    int lane = tid & 31;
    int pxA  = lane * 4;
    int pxB  = 128 + lane * 4;
    int oblk = blockIdx.y * 64;
    int pblk = blockIdx.x * 256;

    int lr = tid >> 5;              // loader row 0..7
    const float2* gW = g_pwT2 + (size_t)lr * 256 + oblk + lane * 2;
    const float*  gM = g_midT + (size_t)lr * 16384 + pblk + lane * 8;

    u64 acc[8][4];
#pragma unroll
    for (int o = 0; o < 8; o++)
#pragma unroll
        for (int j = 0; j < 4; j++) acc[o][j] = 0ull;

    // prefetch stage 0
    cp16(&sW[0][lr][lane * 2], gW);
    cp16(&sM[0][lr][lane * 8], gM);
    cp16(&sM[0][lr][lane * 8 + 4], gM + 4);
    cp_commit();

#pragma unroll 1
    for (int s = 0; s < 32; s++) {
        int buf = s & 1;
        if (s < 31) {
            const float2* w_src = gW + (size_t)(s + 1) * 8 * 256;
            const float*  m_src = gM + (size_t)(s + 1) * 8 * 16384;
            cp16(&sW[buf ^ 1][lr][lane * 2], w_src);
            cp16(&sM[buf ^ 1][lr][lane * 8], m_src);
            cp16(&sM[buf ^ 1][lr][lane * 8 + 4], m_src + 4);
            cp_commit();
            cp_wait<1>();
        } else {
            cp_wait<0>();
        }
        __syncthreads();
#pragma unroll
        for (int k = 0; k < 8; k++) {
            const ulonglong2* wp = (const ulonglong2*)&sW[buf][k][og * 8];
            ulonglong2 w01 = wp[0];
            ulonglong2 w23 = wp[1];
            ulonglong2 w45 = wp[2];
            ulonglong2 w67 = wp[3];
            ulonglong2 mA = *(const ulonglong2*)&sM[buf][k][pxA];
            ulonglong2 mB = *(const ulonglong2*)&sM[buf][k][pxB];
            acc[0][0] = ffma2_(w01.x, mA.x, acc[0][0]);
            acc[0][1] = ffma2_(w01.x, mA.y, acc[0][1]);
            acc[0][2] = ffma2_(w01.x, mB.x, acc[0][2]);
            acc[0][3] = ffma2_(w01.x, mB.y, acc[0][3]);
            acc[1][0] = ffma2_(w01.y, mA.x, acc[1][0]);
            acc[1][1] = ffma2_(w01.y, mA.y, acc[1][1]);
            acc[1][2] = ffma2_(w01.y, mB.x, acc[1][2]);
            acc[1][3] = ffma2_(w01.y, mB.y, acc[1][3]);
            acc[2][0] = ffma2_(w23.x, mA.x, acc[2][0]);
            acc[2][1] = ffma2_(w23.x, mA.y, acc[2][1]);
            acc[2][2] = ffma2_(w23.x, mB.x, acc[2][2]);
            acc[2][3] = ffma2_(w23.x, mB.y, acc[2][3]);
            acc[3][0] = ffma2_(w23.y, mA.x, acc[3][0]);
            acc[3][1] = ffma2_(w23.y, mA.y, acc[3][1]);
            acc[3][2] = ffma2_(w23.y, mB.x, acc[3][2]);
            acc[3][3] = ffma2_(w23.y, mB.y, acc[3][3]);
            acc[4][0] = ffma2_(w45.x, mA.x, acc[4][0]);
            acc[4][1] = ffma2_(w45.x, mA.y, acc[4][1]);
            acc[4][2] = ffma2_(w45.x, mB.x, acc[4][2]);
            acc[4][3] = ffma2_(w45.x, mB.y, acc[4][3]);
            acc[5][0] = ffma2_(w45.y, mA.x, acc[5][0]);
            acc[5][1] = ffma2_(w45.y, mA.y, acc[5][1]);
            acc[5][2] = ffma2_(w45.y, mB.x, acc[5][2]);
            acc[5][3] = ffma2_(w45.y, mB.y, acc[5][3]);
            acc[6][0] = ffma2_(w67.x, mA.x, acc[6][0]);
            acc[6][1] = ffma2_(w67.x, mA.y, acc[6][1]);
            acc[6][2] = ffma2_(w67.x, mB.x, acc[6][2]);
            acc[6][3] = ffma2_(w67.x, mB.y, acc[6][3]);
            acc[7][0] = ffma2_(w67.y, mA.x, acc[7][0]);
            acc[7][1] = ffma2_(w67.y, mA.y, acc[7][1]);
            acc[7][2] = ffma2_(w67.y, mB.x, acc[7][2]);
            acc[7][3] = ffma2_(w67.y, mB.y, acc[7][3]);
        }
        __syncthreads();
    }

    int b  = pblk >> 12;
    int hw = pblk & 4095;
    float* ob = out + (size_t)b * 256 * 4096 + hw;
#pragma unroll
    for (int o = 0; o < 8; o++) {
        int oo = oblk + og * 8 + o;
        float bias = __ldg(g_bias + oo);
        float l0, h0, l1, h1;
        float4 r;
        upk2(acc[o][0], l0, h0);
        upk2(acc[o][1], l1, h1);
        r.x = fmaxf(l0 + bias, 0.f);
        r.y = fmaxf(h0 + bias, 0.f);
        r.z = fmaxf(l1 + bias, 0.f);
        r.w = fmaxf(h1 + bias, 0.f);
        *(float4*)(ob + (size_t)oo * 4096 + pxA) = r;
        upk2(acc[o][2], l0, h0);
        upk2(acc[o][3], l1, h1);
        r.x = fmaxf(l0 + bias, 0.f);
        r.y = fmaxf(h0 + bias, 0.f);
        r.z = fmaxf(l1 + bias, 0.f);
        r.w = fmaxf(h1 + bias, 0.f);
        *(float4*)(ob + (size_t)oo * 4096 + pxB) = r;
    }
}

// ---------------- launch ----------------
extern "C" void kernel_launch(void* const* d_in, const int* in_sizes, int n_in,
                              void* d_out, int out_size) {
    const float* x    = (const float*)d_in[0];
    const float* gf   = (const float*)d_in[1];
    const float* offw = (const float*)d_in[2];
    const float* og   = (const float*)d_in[3];
    const float* obt  = (const float*)d_in[4];
    const float* om   = (const float*)d_in[5];
    const float* ov   = (const float*)d_in[6];
    const float* dww  = (const float*)d_in[7];
    const float* pww  = (const float*)d_in[8];
    const float* bg   = (const float*)d_in[9];
    const float* bb   = (const float*)d_in[10];
    const float* bm   = (const float*)d_in[11];
    const float* bv   = (const float*)d_in[12];
    float* out = (float*)d_out;

    k_transpose<<<dim3(128, 8, 4), dim3(32, 8)>>>(x);
    k_prep<<<256, 256>>>(pww, bg, bb, bm, bv);
    k_offset<<<256, 64>>>(gf, offw, og, obt, om, ov);
    k_sample<<<1024, 256>>>(dww);
    k_gemm<<<dim3(64, 4), 256>>>(out);
}

// round 6
// speedup vs baseline: 1.2171x; 1.2171x over previous
#include <cuda_runtime.h>
#include <cuda_bf16.h>
#include <cstdint>
#include <cstring>

#define EPS 1e-5f
typedef unsigned long long u64;

// ---------------- f32x2 packed helpers ----------------
__device__ __forceinline__ u64 pk2(float lo, float hi) {
    u64 r;
    asm("mov.b64 %0, {%1, %2};" : "=l"(r) : "f"(lo), "f"(hi));
    return r;
}
__device__ __forceinline__ void upk2(u64 v, float& lo, float& hi) {
    asm("mov.b64 {%0, %1}, %2;" : "=f"(lo), "=f"(hi) : "l"(v));
}
__device__ __forceinline__ u64 ffma2_(u64 a, u64 b, u64 c) {
    u64 d;
    asm("fma.rn.f32x2 %0, %1, %2, %3;" : "=l"(d) : "l"(a), "l"(b), "l"(c));
    return d;
}
__device__ __forceinline__ u64 fmul2_(u64 a, u64 b) {
    u64 d;
    asm("mul.rn.f32x2 %0, %1, %2;" : "=l"(d) : "l"(a), "l"(b));
    return d;
}

// ---------------- cp.async helpers ----------------
__device__ __forceinline__ void cp16(void* smem_dst, const void* gsrc) {
    unsigned s = (unsigned)__cvta_generic_to_shared(smem_dst);
    asm volatile("cp.async.cg.shared.global [%0], [%1], 16;" :: "r"(s), "l"(gsrc));
}
__device__ __forceinline__ void cp_commit() {
    asm volatile("cp.async.commit_group;");
}
template <int N>
__device__ __forceinline__ void cp_wait() {
    asm volatile("cp.async.wait_group %0;" :: "n"(N));
}

// ---------------- mma helpers (legacy HMMA path, plain sm_103 OK) ----------------
__device__ __forceinline__ uint32_t smem_u32(const void* p) {
    uint32_t a;
    asm("{ .reg .u64 t; cvta.to.shared.u64 t, %1; cvt.u32.u64 %0, t; }" : "=r"(a) : "l"(p));
    return a;
}
__device__ __forceinline__ void ldsm4(uint32_t& r0, uint32_t& r1, uint32_t& r2, uint32_t& r3,
                                      uint32_t addr) {
    asm volatile("ldmatrix.sync.aligned.m8n8.x4.shared.b16 {%0,%1,%2,%3}, [%4];"
                 : "=r"(r0), "=r"(r1), "=r"(r2), "=r"(r3) : "r"(addr));
}
__device__ __forceinline__ void mma_bf16(float* d, const uint32_t* a, uint32_t b0, uint32_t b1) {
    asm volatile(
        "mma.sync.aligned.m16n8k16.row.col.f32.bf16.bf16.f32 "
        "{%0,%1,%2,%3}, {%4,%5,%6,%7}, {%8,%9}, {%0,%1,%2,%3};"
        : "+f"(d[0]), "+f"(d[1]), "+f"(d[2]), "+f"(d[3])
        : "r"(a[0]), "r"(a[1]), "r"(a[2]), "r"(a[3]), "r"(b0), "r"(b1));
}

// ---------------- scratch ----------------
__device__ float  g_x_nhwc[4 * 64 * 64 * 256];   // [b][h][w][c]
__device__ int4   g_off4[4 * 9 * 64 * 64];
__device__ float4 g_cw[4 * 9 * 64 * 64];
__device__ float  g_bias[256];
__device__ __nv_bfloat16 g_whi[256 * 256];       // [o][c]
__device__ __nv_bfloat16 g_wlo[256 * 256];
__device__ __nv_bfloat16 g_mhi[16384 * 256];     // [px][c]
__device__ __nv_bfloat16 g_mlo[16384 * 256];

// ---------------- kernel 1: NCHW -> NHWC transpose ----------------
__global__ void k_transpose(const float* __restrict__ x) {
    __shared__ float tile[32][33];
    int b  = blockIdx.z;
    int s0 = blockIdx.x * 32;
    int c0 = blockIdx.y * 32;
    int tx = threadIdx.x, ty = threadIdx.y;  // (32, 8)
    const float* xb = x + (size_t)b * 256 * 4096;
    float* ob = g_x_nhwc + (size_t)b * 4096 * 256;
#pragma unroll
    for (int i = 0; i < 32; i += 8)
        tile[ty + i][tx] = xb[(c0 + ty + i) * 4096 + s0 + tx];
    __syncthreads();
#pragma unroll
    for (int i = 0; i < 32; i += 8)
        ob[(s0 + ty + i) * 256 + c0 + tx] = tile[tx][ty + i];
}

// ---------------- kernel 2: weight prep (split bf16, fold BN) ----------------
__global__ void k_prep(const float* __restrict__ pw, const float* __restrict__ bg,
                       const float* __restrict__ bb, const float* __restrict__ bm,
                       const float* __restrict__ bv) {
    int idx = blockIdx.x * 256 + threadIdx.x;   // 65536 total
    int c = idx & 255;
    int o = idx >> 8;
    float s = bg[o] * rsqrtf(bv[o] + EPS);
    float w = __ldg(pw + o * 256 + c) * s;
    __nv_bfloat16 hi = __float2bfloat16(w);
    __nv_bfloat16 lo = __float2bfloat16(w - __bfloat162float(hi));
    g_whi[o * 256 + c] = hi;
    g_wlo[o * 256 + c] = lo;
    if (idx < 256) {
        float s2 = bg[idx] * rsqrtf(bv[idx] + EPS);
        g_bias[idx] = bb[idx] - bm[idx] * s2;
    }
}

// ---------------- kernel 3: offset conv + sampling params ----------------
__global__ void k_offset(const float* __restrict__ gf, const float* __restrict__ offw,
                         const float* __restrict__ og, const float* __restrict__ obt,
                         const float* __restrict__ om, const float* __restrict__ ov) {
    __shared__ __align__(16) float2 s_w2[9][64][10];
    int bh = blockIdx.x;
    int b = bh >> 6, h = bh & 63;
    int w = threadIdx.x;   // 0..63

    for (int i = w; i < 9 * 64 * 9; i += 64) {
        int t = i % 9;
        int g = (i / 9) & 63;
        int k = i / 576;
        float wdy = offw[(2 * k) * 576 + g * 9 + t];
        float wdx = offw[(2 * k + 1) * 576 + g * 9 + t];
        s_w2[k][g][t] = make_float2(wdy, wdx);
    }
    __syncthreads();

    u64 acc[9];
#pragma unroll
    for (int k = 0; k < 9; k++) acc[k] = 0ull;

    const float* gfb = gf + (size_t)b * 64 * 64 * 64;
    for (int g = 0; g < 64; g++) {
        float a[9];
#pragma unroll
        for (int r = 0; r < 3; r++) {
            int hh = h + r - 1;
            bool hv = (unsigned)hh < 64u;
#pragma unroll
            for (int q = 0; q < 3; q++) {
                int ww = w + q - 1;
                bool wv2 = (unsigned)ww < 64u;
                a[r * 3 + q] = (hv && wv2) ? __ldg(gfb + (g * 64 + hh) * 64 + ww) : 0.f;
            }
        }
        u64 a2[9];
#pragma unroll
        for (int t = 0; t < 9; t++) a2[t] = pk2(a[t], a[t]);
#pragma unroll
        for (int k = 0; k < 9; k++) {
            const u64* wr = (const u64*)&s_w2[k][g][0];
            ulonglong2 w01 = *(const ulonglong2*)(wr + 0);
            ulonglong2 w23 = *(const ulonglong2*)(wr + 2);
            ulonglong2 w45 = *(const ulonglong2*)(wr + 4);
            ulonglong2 w67 = *(const ulonglong2*)(wr + 6);
            u64 w8 = wr[8];
            acc[k] = ffma2_(w01.x, a2[0], acc[k]);
            acc[k] = ffma2_(w01.y, a2[1], acc[k]);
            acc[k] = ffma2_(w23.x, a2[2], acc[k]);
            acc[k] = ffma2_(w23.y, a2[3], acc[k]);
            acc[k] = ffma2_(w45.x, a2[4], acc[k]);
            acc[k] = ffma2_(w45.y, a2[5], acc[k]);
            acc[k] = ffma2_(w67.x, a2[6], acc[k]);
            acc[k] = ffma2_(w67.y, a2[7], acc[k]);
            acc[k] = ffma2_(w8,    a2[8], acc[k]);
        }
    }

#pragma unroll
    for (int k = 0; k < 9; k++) {
        float dyr, dxr;
        upk2(acc[k], dyr, dxr);
        int j0 = 2 * k, j1 = 2 * k + 1;
        float s0 = og[j0] * rsqrtf(ov[j0] + EPS);
        float s1 = og[j1] * rsqrtf(ov[j1] + EPS);
        float dy = fmaxf((dyr - om[j0]) * s0 + obt[j0], 0.f);
        float dx = fmaxf((dxr - om[j1]) * s1 + obt[j1], 0.f);
        float ky = (float)((k / 3) - 1) * 2.0f;   // DIL = 2
        float kx = (float)((k % 3) - 1) * 2.0f;
        float gy = (float)h + ky + dy;
        float gx = (float)w + kx + dx;
        float y0f = floorf(gy), x0f = floorf(gx);
        float wy = gy - y0f, wx = gx - x0f;
        float omwy = 1.f - wy, omwx = 1.f - wx;
        int y0 = (int)y0f, x0 = (int)x0f;
        bool yv0 = (unsigned)y0 < 64u;
        bool yv1 = (unsigned)(y0 + 1) < 64u;
        bool xv0 = (unsigned)x0 < 64u;
        bool xv1 = (unsigned)(x0 + 1) < 64u;
        int y0c = min(max(y0, 0), 63);
        int y1c = min(max(y0 + 1, 0), 63);
        int x0c = min(max(x0, 0), 63);
        int x1c = min(max(x0 + 1, 0), 63);
        int idx = ((b * 9 + k) * 64 + h) * 64 + w;
        g_off4[idx] = make_int4((y0c * 64 + x0c) * 256, (y0c * 64 + x1c) * 256,
                                (y1c * 64 + x0c) * 256, (y1c * 64 + x1c) * 256);
        g_cw[idx] = make_float4(omwy * omwx * (float)(yv0 && xv0),
                                omwy * wx   * (float)(yv0 && xv1),
                                wy * omwx   * (float)(yv1 && xv0),
                                wy * wx     * (float)(yv1 && xv1));
    }
}

// ---------------- kernel 4: sample + depthwise -> split bf16 mid [px][c] ----------------
__global__ __launch_bounds__(256, 3) void k_sample(const float* __restrict__ dw) {
    __shared__ __align__(16) int4 s_off[9][16];
    __shared__ __align__(16) u64 s_cw[9][16][4];

    int t  = blockIdx.x;
    int w0 = (t & 3) << 4;
    int h  = (t >> 2) & 63;
    int b  = t >> 8;
    int tid = threadIdx.x;

    if (tid < 144) {
        int k = tid / 16, p = tid & 15;
        int idx = ((b * 9 + k) * 64 + h) * 64 + w0 + p;
        s_off[k][p] = g_off4[idx];
        float4 cw = g_cw[idx];
        s_cw[k][p][0] = pk2(cw.x, cw.x);
        s_cw[k][p][1] = pk2(cw.y, cw.y);
        s_cw[k][p][2] = pk2(cw.z, cw.z);
        s_cw[k][p][3] = pk2(cw.w, cw.w);
    }

    int cg = tid & 63;
    int c  = cg * 4;
    int ps = tid >> 6;

    u64 dwv[9][2];
#pragma unroll
    for (int k = 0; k < 9; k++) {
        dwv[k][0] = pk2(__ldg(dw + c * 9 + k),       __ldg(dw + (c + 1) * 9 + k));
        dwv[k][1] = pk2(__ldg(dw + (c + 2) * 9 + k), __ldg(dw + (c + 3) * 9 + k));
    }
    __syncthreads();

    const float* xb = g_x_nhwc + (size_t)b * 4096 * 256 + c;
    int pgbase = b * 4096 + h * 64 + w0;
#pragma unroll 2
    for (int i = 0; i < 4; i++) {
        int p = ps * 4 + i;
        u64 a0 = 0ull, a1 = 0ull;
#pragma unroll
        for (int k = 0; k < 9; k++) {
            int4 o4 = s_off[k][p];
            float4 v00 = __ldg((const float4*)(xb + o4.x));
            float4 v01 = __ldg((const float4*)(xb + o4.y));
            float4 v10 = __ldg((const float4*)(xb + o4.z));
            float4 v11 = __ldg((const float4*)(xb + o4.w));
            ulonglong2 c01 = *(const ulonglong2*)&s_cw[k][p][0];
            ulonglong2 c23 = *(const ulonglong2*)&s_cw[k][p][2];
            const u64* q00 = (const u64*)&v00;
            const u64* q01 = (const u64*)&v01;
            const u64* q10 = (const u64*)&v10;
            const u64* q11 = (const u64*)&v11;
            u64 b0 = fmul2_(c01.x, q00[0]);
            u64 b1 = fmul2_(c01.x, q00[1]);
            b0 = ffma2_(c01.y, q01[0], b0);
            b1 = ffma2_(c01.y, q01[1], b1);
            b0 = ffma2_(c23.x, q10[0], b0);
            b1 = ffma2_(c23.x, q10[1], b1);
            b0 = ffma2_(c23.y, q11[0], b0);
            b1 = ffma2_(c23.y, q11[1], b1);
            a0 = ffma2_(dwv[k][0], b0, a0);
            a1 = ffma2_(dwv[k][1], b1, a1);
        }
        float f0, f1, f2, f3;
        upk2(a0, f0, f1);
        upk2(a1, f2, f3);

        __nv_bfloat162 h01 = __floats2bfloat162_rn(f0, f1);
        __nv_bfloat162 h23 = __floats2bfloat162_rn(f2, f3);
        float2 r01 = __bfloat1622float2(h01);
        float2 r23 = __bfloat1622float2(h23);
        __nv_bfloat162 l01 = __floats2bfloat162_rn(f0 - r01.x, f1 - r01.y);
        __nv_bfloat162 l23 = __floats2bfloat162_rn(f2 - r23.x, f3 - r23.y);

        size_t off = (size_t)(pgbase + p) * 256 + c;
        uint2 hv, lv;
        memcpy(&hv.x, &h01, 4); memcpy(&hv.y, &h23, 4);
        memcpy(&lv.x, &l01, 4); memcpy(&lv.y, &l23, 4);
        *(uint2*)(g_mhi + off) = hv;
        *(uint2*)(g_mlo + off) = lv;
    }
}

// ---------------- kernel 5: bf16-split GEMM via mma.sync + BN/ReLU ----------------
// CTA: 128 o x 128 px, K=256 in 4 chunks of 64. 8 warps, warp tile 64o x 32px.
// smem: [stage2][sel2][128 rows][72 bf16] for W and M (144B padded rows).
#define SELB  18432
#define STGB  36864
#define MBASE 73728
__global__ __launch_bounds__(256, 1) void k_gemm_mma(float* __restrict__ out) {
    extern __shared__ __align__(1024) char dyn[];
    const int tid  = threadIdx.x;
    const int warp = tid >> 5, lane = tid & 31;
    const int wo   = warp >> 2;      // 0..1  (o dim)
    const int wp   = warp & 3;       // 0..3  (px dim)
    const int pb   = blockIdx.x, ob = blockIdx.y;

    const uint32_t uS = smem_u32(dyn);

    float acc[4][4][4];
#pragma unroll
    for (int mt = 0; mt < 4; mt++)
#pragma unroll
        for (int nt = 0; nt < 4; nt++)
#pragma unroll
            for (int j = 0; j < 4; j++) acc[mt][nt][j] = 0.f;

    // ldmatrix per-lane offset within a 16x16 tile (bytes)
    const int g  = lane >> 3, rr = lane & 7;
    const int lmo = ((g & 1) * 8 + rr) * 144 + (g >> 1) * 16;

    const __nv_bfloat16* gsrc[4] = {g_whi, g_wlo, g_mhi, g_mlo};

    // chunk loader: 16 cp16 per thread
    auto ldchunk = [&](int ch, int st) {
#pragma unroll
        for (int a = 0; a < 4; a++) {
            const __nv_bfloat16* gp = gsrc[a];
            size_t rowbase = (a < 2) ? (size_t)(ob * 128) : (size_t)(pb * 128);
            char* dbase = dyn + ((a < 2) ? 0 : MBASE) + st * STGB + (a & 1) * SELB;
#pragma unroll
            for (int i = 0; i < 4; i++) {
                int idx = tid + i * 256;
                int r = idx >> 3, kc8 = (idx & 7) * 8;
                cp16(dbase + r * 144 + kc8 * 2,
                     gp + (rowbase + r) * 256 + ch * 64 + kc8);
            }
        }
    };

    ldchunk(0, 0);
    cp_commit();

#pragma unroll 1
    for (int ch = 0; ch < 4; ch++) {
        int st = ch & 1;
        if (ch < 3) {
            ldchunk(ch + 1, st ^ 1);
            cp_commit();
            cp_wait<1>();
        } else {
            cp_wait<0>();
        }
        __syncthreads();

        uint32_t wbase = uS + st * STGB + (wo * 64) * 144 + lmo;
        uint32_t bbase = uS + MBASE + st * STGB + (wp * 32) * 144 + lmo;

#pragma unroll
        for (int ks = 0; ks < 4; ks++) {
            int kb = ks * 32;   // 16 bf16 = 32 bytes
            uint32_t bh[8], bl[8];
            ldsm4(bh[0], bh[1], bh[2], bh[3], bbase + kb);
            ldsm4(bh[4], bh[5], bh[6], bh[7], bbase + 16 * 144 + kb);
            ldsm4(bl[0], bl[1], bl[2], bl[3], bbase + SELB + kb);
            ldsm4(bl[4], bl[5], bl[6], bl[7], bbase + SELB + 16 * 144 + kb);
#pragma unroll
            for (int mt = 0; mt < 4; mt++) {
                uint32_t ah[4], al[4];
                uint32_t abase = wbase + mt * 16 * 144 + kb;
                ldsm4(ah[0], ah[1], ah[2], ah[3], abase);
                ldsm4(al[0], al[1], al[2], al[3], abase + SELB);
#pragma unroll
                for (int nt = 0; nt < 4; nt++) {
                    uint32_t b0h = bh[(nt & 1) + (nt >> 1) * 4];
                    uint32_t b1h = bh[(nt & 1) + (nt >> 1) * 4 + 2];
                    uint32_t b0l = bl[(nt & 1) + (nt >> 1) * 4];
                    uint32_t b1l = bl[(nt & 1) + (nt >> 1) * 4 + 2];
                    mma_bf16(acc[mt][nt], ah, b0h, b1h);   // hi*hi
                    mma_bf16(acc[mt][nt], ah, b0l, b1l);   // hi*lo
                    mma_bf16(acc[mt][nt], al, b0h, b1h);   // lo*hi
                }
            }
        }
        __syncthreads();
    }

    // epilogue: bias + relu, direct stores (float2 -> full 32B sectors)
    int pxg = pb * 128;
    int bidx = pxg >> 12;
    int hw0  = pxg & 4095;
    float* obase = out + (size_t)bidx * 1048576;
    int o_w  = ob * 128 + wo * 64;
    int px_w = hw0 + wp * 32;
#pragma unroll
    for (int mt = 0; mt < 4; mt++) {
        int r0 = o_w + mt * 16 + (lane >> 2);
        float bias0 = __ldg(g_bias + r0);
        float bias1 = __ldg(g_bias + r0 + 8);
        float* row0 = obase + (size_t)r0 * 4096;
        float* row1 = row0 + 8 * 4096;
#pragma unroll
        for (int nt = 0; nt < 4; nt++) {
            int px = px_w + nt * 8 + (lane & 3) * 2;
            float2 v0 = make_float2(fmaxf(acc[mt][nt][0] + bias0, 0.f),
                                    fmaxf(acc[mt][nt][1] + bias0, 0.f));
            float2 v1 = make_float2(fmaxf(acc[mt][nt][2] + bias1, 0.f),
                                    fmaxf(acc[mt][nt][3] + bias1, 0.f));
            *(float2*)(row0 + px) = v0;
            *(float2*)(row1 + px) = v1;
        }
    }
}

// ---------------- launch ----------------
extern "C" void kernel_launch(void* const* d_in, const int* in_sizes, int n_in,
                              void* d_out, int out_size) {
    const float* x    = (const float*)d_in[0];
    const float* gf   = (const float*)d_in[1];
    const float* offw = (const float*)d_in[2];
    const float* og   = (const float*)d_in[3];
    const float* obt  = (const float*)d_in[4];
    const float* om   = (const float*)d_in[5];
    const float* ov   = (const float*)d_in[6];
    const float* dww  = (const float*)d_in[7];
    const float* pww  = (const float*)d_in[8];
    const float* bg   = (const float*)d_in[9];
    const float* bb   = (const float*)d_in[10];
    const float* bm   = (const float*)d_in[11];
    const float* bv   = (const float*)d_in[12];
    float* out = (float*)d_out;

    cudaFuncSetAttribute(k_gemm_mma, cudaFuncAttributeMaxDynamicSharedMemorySize, 147456);

    k_transpose<<<dim3(128, 8, 4), dim3(32, 8)>>>(x);
    k_prep<<<256, 256>>>(pww, bg, bb, bm, bv);
    k_offset<<<256, 64>>>(gf, offw, og, obt, om, ov);
    k_sample<<<1024, 256>>>(dww);
    k_gemm_mma<<<dim3(128, 2), 256, 147456>>>(out);
}

// round 7
// speedup vs baseline: 1.5498x; 1.2733x over previous
#include <cuda_runtime.h>
#include <cuda_bf16.h>
#include <cuda_fp16.h>
#include <cstdint>
#include <cstring>

#define EPS 1e-5f
typedef unsigned long long u64;

// ---------------- f32x2 packed helpers ----------------
__device__ __forceinline__ u64 pk2(float lo, float hi) {
    u64 r;
    asm("mov.b64 %0, {%1, %2};" : "=l"(r) : "f"(lo), "f"(hi));
    return r;
}
__device__ __forceinline__ void upk2(u64 v, float& lo, float& hi) {
    asm("mov.b64 {%0, %1}, %2;" : "=f"(lo), "=f"(hi) : "l"(v));
}
__device__ __forceinline__ u64 ffma2_(u64 a, u64 b, u64 c) {
    u64 d;
    asm("fma.rn.f32x2 %0, %1, %2, %3;" : "=l"(d) : "l"(a), "l"(b), "l"(c));
    return d;
}
__device__ __forceinline__ u64 fmul2_(u64 a, u64 b) {
    u64 d;
    asm("mul.rn.f32x2 %0, %1, %2;" : "=l"(d) : "l"(a), "l"(b));
    return d;
}
__device__ __forceinline__ __half2 u2h(uint32_t u) {
    __half2 h;
    memcpy(&h, &u, 4);
    return h;
}

// ---------------- cp.async helpers ----------------
__device__ __forceinline__ void cp16(void* smem_dst, const void* gsrc) {
    unsigned s = (unsigned)__cvta_generic_to_shared(smem_dst);
    asm volatile("cp.async.cg.shared.global [%0], [%1], 16;" :: "r"(s), "l"(gsrc));
}
__device__ __forceinline__ void cp_commit() {
    asm volatile("cp.async.commit_group;");
}
template <int N>
__device__ __forceinline__ void cp_wait() {
    asm volatile("cp.async.wait_group %0;" :: "n"(N));
}

// ---------------- mma helpers ----------------
__device__ __forceinline__ uint32_t smem_u32(const void* p) {
    uint32_t a;
    asm("{ .reg .u64 t; cvta.to.shared.u64 t, %1; cvt.u32.u64 %0, t; }" : "=r"(a) : "l"(p));
    return a;
}
__device__ __forceinline__ void ldsm4(uint32_t& r0, uint32_t& r1, uint32_t& r2, uint32_t& r3,
                                      uint32_t addr) {
    asm volatile("ldmatrix.sync.aligned.m8n8.x4.shared.b16 {%0,%1,%2,%3}, [%4];"
                 : "=r"(r0), "=r"(r1), "=r"(r2), "=r"(r3) : "r"(addr));
}
__device__ __forceinline__ void mma_bf16(float* d, const uint32_t* a, uint32_t b0, uint32_t b1) {
    asm volatile(
        "mma.sync.aligned.m16n8k16.row.col.f32.bf16.bf16.f32 "
        "{%0,%1,%2,%3}, {%4,%5,%6,%7}, {%8,%9}, {%0,%1,%2,%3};"
        : "+f"(d[0]), "+f"(d[1]), "+f"(d[2]), "+f"(d[3])
        : "r"(a[0]), "r"(a[1]), "r"(a[2]), "r"(a[3]), "r"(b0), "r"(b1));
}

// ---------------- scratch ----------------
__device__ __half g_x_h[4 * 64 * 64 * 256];      // [b][h][w][c] fp16
__device__ int4   g_off4[4 * 9 * 64 * 64];       // corner elem offsets (half units)
__device__ uint4  g_cwh[4 * 9 * 64 * 64];        // 4 duplicated half2 corner weights
__device__ float  g_bias[256];
__device__ __nv_bfloat16 g_whi[256 * 256];       // [o][c]
__device__ __nv_bfloat16 g_wlo[256 * 256];
__device__ __nv_bfloat16 g_mhi[16384 * 256];     // [px][c]
__device__ __nv_bfloat16 g_mlo[16384 * 256];

// ---------------- kernel 1: NCHW fp32 -> NHWC fp16 ----------------
__global__ void k_transpose(const float* __restrict__ x) {
    __shared__ float tile[32][33];
    int b  = blockIdx.z;
    int s0 = blockIdx.x * 32;
    int c0 = blockIdx.y * 32;
    int tx = threadIdx.x, ty = threadIdx.y;  // (32, 8)
    const float* xb = x + (size_t)b * 256 * 4096;
    __half* ob = g_x_h + (size_t)b * 4096 * 256;
#pragma unroll
    for (int i = 0; i < 32; i += 8)
        tile[ty + i][tx] = xb[(c0 + ty + i) * 4096 + s0 + tx];
    __syncthreads();
    int tid = ty * 32 + tx;
#pragma unroll
    for (int j = 0; j < 2; j++) {
        int it = tid + j * 256;      // 0..511 : r = it>>4 (32 rows), pc = it&15
        int r  = it >> 4, pc = it & 15;
        __half2 v = __floats2half2_rn(tile[pc * 2][r], tile[pc * 2 + 1][r]);
        *(__half2*)(ob + (size_t)(s0 + r) * 256 + c0 + pc * 2) = v;
    }
}

// ---------------- kernel 2: weight prep (split bf16, fold BN) ----------------
__global__ void k_prep(const float* __restrict__ pw, const float* __restrict__ bg,
                       const float* __restrict__ bb, const float* __restrict__ bm,
                       const float* __restrict__ bv) {
    int idx = blockIdx.x * 256 + threadIdx.x;   // 65536 total
    int c = idx & 255;
    int o = idx >> 8;
    float s = bg[o] * rsqrtf(bv[o] + EPS);
    float w = __ldg(pw + o * 256 + c) * s;
    __nv_bfloat16 hi = __float2bfloat16(w);
    __nv_bfloat16 lo = __float2bfloat16(w - __bfloat162float(hi));
    g_whi[o * 256 + c] = hi;
    g_wlo[o * 256 + c] = lo;
    if (idx < 256) {
        float s2 = bg[idx] * rsqrtf(bv[idx] + EPS);
        g_bias[idx] = bb[idx] - bm[idx] * s2;
    }
}

// ---------------- kernel 3: offset conv + sampling params ----------------
__global__ void k_offset(const float* __restrict__ gf, const float* __restrict__ offw,
                         const float* __restrict__ og, const float* __restrict__ obt,
                         const float* __restrict__ om, const float* __restrict__ ov) {
    __shared__ __align__(16) float2 s_w2[9][64][10];
    int bh = blockIdx.x;
    int b = bh >> 6, h = bh & 63;
    int w = threadIdx.x;   // 0..63

    for (int i = w; i < 9 * 64 * 9; i += 64) {
        int t = i % 9;
        int g = (i / 9) & 63;
        int k = i / 576;
        float wdy = offw[(2 * k) * 576 + g * 9 + t];
        float wdx = offw[(2 * k + 1) * 576 + g * 9 + t];
        s_w2[k][g][t] = make_float2(wdy, wdx);
    }
    __syncthreads();

    u64 acc[9];
#pragma unroll
    for (int k = 0; k < 9; k++) acc[k] = 0ull;

    const float* gfb = gf + (size_t)b * 64 * 64 * 64;
    for (int g = 0; g < 64; g++) {
        float a[9];
#pragma unroll
        for (int r = 0; r < 3; r++) {
            int hh = h + r - 1;
            bool hv = (unsigned)hh < 64u;
#pragma unroll
            for (int q = 0; q < 3; q++) {
                int ww = w + q - 1;
                bool wv2 = (unsigned)ww < 64u;
                a[r * 3 + q] = (hv && wv2) ? __ldg(gfb + (g * 64 + hh) * 64 + ww) : 0.f;
            }
        }
        u64 a2[9];
#pragma unroll
        for (int t = 0; t < 9; t++) a2[t] = pk2(a[t], a[t]);
#pragma unroll
        for (int k = 0; k < 9; k++) {
            const u64* wr = (const u64*)&s_w2[k][g][0];
            ulonglong2 w01 = *(const ulonglong2*)(wr + 0);
            ulonglong2 w23 = *(const ulonglong2*)(wr + 2);
            ulonglong2 w45 = *(const ulonglong2*)(wr + 4);
            ulonglong2 w67 = *(const ulonglong2*)(wr + 6);
            u64 w8 = wr[8];
            acc[k] = ffma2_(w01.x, a2[0], acc[k]);
            acc[k] = ffma2_(w01.y, a2[1], acc[k]);
            acc[k] = ffma2_(w23.x, a2[2], acc[k]);
            acc[k] = ffma2_(w23.y, a2[3], acc[k]);
            acc[k] = ffma2_(w45.x, a2[4], acc[k]);
            acc[k] = ffma2_(w45.y, a2[5], acc[k]);
            acc[k] = ffma2_(w67.x, a2[6], acc[k]);
            acc[k] = ffma2_(w67.y, a2[7], acc[k]);
            acc[k] = ffma2_(w8,    a2[8], acc[k]);
        }
    }

#pragma unroll
    for (int k = 0; k < 9; k++) {
        float dyr, dxr;
        upk2(acc[k], dyr, dxr);
        int j0 = 2 * k, j1 = 2 * k + 1;
        float s0 = og[j0] * rsqrtf(ov[j0] + EPS);
        float s1 = og[j1] * rsqrtf(ov[j1] + EPS);
        float dy = fmaxf((dyr - om[j0]) * s0 + obt[j0], 0.f);
        float dx = fmaxf((dxr - om[j1]) * s1 + obt[j1], 0.f);
        float ky = (float)((k / 3) - 1) * 2.0f;   // DIL = 2
        float kx = (float)((k % 3) - 1) * 2.0f;
        float gy = (float)h + ky + dy;
        float gx = (float)w + kx + dx;
        float y0f = floorf(gy), x0f = floorf(gx);
        float wy = gy - y0f, wx = gx - x0f;
        float omwy = 1.f - wy, omwx = 1.f - wx;
        int y0 = (int)y0f, x0 = (int)x0f;
        bool yv0 = (unsigned)y0 < 64u;
        bool yv1 = (unsigned)(y0 + 1) < 64u;
        bool xv0 = (unsigned)x0 < 64u;
        bool xv1 = (unsigned)(x0 + 1) < 64u;
        int y0c = min(max(y0, 0), 63);
        int y1c = min(max(y0 + 1, 0), 63);
        int x0c = min(max(x0, 0), 63);
        int x1c = min(max(x0 + 1, 0), 63);
        int idx = ((b * 9 + k) * 64 + h) * 64 + w;
        g_off4[idx] = make_int4((y0c * 64 + x0c) * 256, (y0c * 64 + x1c) * 256,
                                (y1c * 64 + x0c) * 256, (y1c * 64 + x1c) * 256);
        float c00 = omwy * omwx * (float)(yv0 && xv0);
        float c01 = omwy * wx   * (float)(yv0 && xv1);
        float c10 = wy * omwx   * (float)(yv1 && xv0);
        float c11 = wy * wx     * (float)(yv1 && xv1);
        __half2 h00 = __float2half2_rn(c00);
        __half2 h01 = __float2half2_rn(c01);
        __half2 h10 = __float2half2_rn(c10);
        __half2 h11 = __float2half2_rn(c11);
        uint4 pack;
        memcpy(&pack.x, &h00, 4);
        memcpy(&pack.y, &h01, 4);
        memcpy(&pack.z, &h10, 4);
        memcpy(&pack.w, &h11, 4);
        g_cwh[idx] = pack;
    }
}

// ---------------- kernel 4: fp16 sample + depthwise -> split bf16 mid [px][c] ----------------
__global__ __launch_bounds__(256, 3) void k_sample(const float* __restrict__ dw) {
    __shared__ __align__(16) int4 s_off[9][16];
    __shared__ __align__(16) uint4 s_cwh[9][16];

    int t  = blockIdx.x;
    int w0 = (t & 3) << 4;
    int h  = (t >> 2) & 63;
    int b  = t >> 8;
    int tid = threadIdx.x;

    if (tid < 144) {
        int k = tid / 16, p = tid & 15;
        int idx = ((b * 9 + k) * 64 + h) * 64 + w0 + p;
        s_off[k][p] = g_off4[idx];
        s_cwh[k][p] = g_cwh[idx];
    }

    int cg = tid & 63;
    int c  = cg * 4;
    int ps = tid >> 6;

    u64 dwv[9][2];
#pragma unroll
    for (int k = 0; k < 9; k++) {
        dwv[k][0] = pk2(__ldg(dw + c * 9 + k),       __ldg(dw + (c + 1) * 9 + k));
        dwv[k][1] = pk2(__ldg(dw + (c + 2) * 9 + k), __ldg(dw + (c + 3) * 9 + k));
    }
    __syncthreads();

    const __half* xh = g_x_h + (size_t)b * 4096 * 256 + c;
    int pgbase = b * 4096 + h * 64 + w0;
#pragma unroll 2
    for (int i = 0; i < 4; i++) {
        int p = ps * 4 + i;
        u64 a0 = 0ull, a1 = 0ull;
#pragma unroll
        for (int k = 0; k < 9; k++) {
            int4 o4 = s_off[k][p];
            uint2 r00 = __ldg((const uint2*)(xh + o4.x));
            uint2 r01 = __ldg((const uint2*)(xh + o4.y));
            uint2 r10 = __ldg((const uint2*)(xh + o4.z));
            uint2 r11 = __ldg((const uint2*)(xh + o4.w));
            uint4 cw = s_cwh[k][p];
            __half2 w00 = u2h(cw.x), w01 = u2h(cw.y), w10 = u2h(cw.z), w11 = u2h(cw.w);
            __half2 bA = __hmul2(w00, u2h(r00.x));
            __half2 bB = __hmul2(w00, u2h(r00.y));
            bA = __hfma2(w01, u2h(r01.x), bA);
            bB = __hfma2(w01, u2h(r01.y), bB);
            bA = __hfma2(w10, u2h(r10.x), bA);
            bB = __hfma2(w10, u2h(r10.y), bB);
            bA = __hfma2(w11, u2h(r11.x), bA);
            bB = __hfma2(w11, u2h(r11.y), bB);
            float2 fA = __half22float2(bA);
            float2 fB = __half22float2(bB);
            a0 = ffma2_(dwv[k][0], pk2(fA.x, fA.y), a0);
            a1 = ffma2_(dwv[k][1], pk2(fB.x, fB.y), a1);
        }
        float f0, f1, f2, f3;
        upk2(a0, f0, f1);
        upk2(a1, f2, f3);

        __nv_bfloat162 h01 = __floats2bfloat162_rn(f0, f1);
        __nv_bfloat162 h23 = __floats2bfloat162_rn(f2, f3);
        float2 r01f = __bfloat1622float2(h01);
        float2 r23f = __bfloat1622float2(h23);
        __nv_bfloat162 l01 = __floats2bfloat162_rn(f0 - r01f.x, f1 - r01f.y);
        __nv_bfloat162 l23 = __floats2bfloat162_rn(f2 - r23f.x, f3 - r23f.y);

        size_t off = (size_t)(pgbase + p) * 256 + c;
        uint2 hv, lv;
        memcpy(&hv.x, &h01, 4); memcpy(&hv.y, &h23, 4);
        memcpy(&lv.x, &l01, 4); memcpy(&lv.y, &l23, 4);
        *(uint2*)(g_mhi + off) = hv;
        *(uint2*)(g_mlo + off) = lv;
    }
}

// ---------------- kernel 5: bf16-split GEMM via mma.sync + BN/ReLU ----------------
#define SELB  18432
#define STGB  36864
#define MBASE 73728
__global__ __launch_bounds__(256, 1) void k_gemm_mma(float* __restrict__ out) {
    extern __shared__ __align__(1024) char dyn[];
    const int tid  = threadIdx.x;
    const int warp = tid >> 5, lane = tid & 31;
    const int wo   = warp >> 2;      // 0..1  (o dim)
    const int wp   = warp & 3;       // 0..3  (px dim)
    const int pb   = blockIdx.x, ob = blockIdx.y;

    const uint32_t uS = smem_u32(dyn);

    float acc[4][4][4];
#pragma unroll
    for (int mt = 0; mt < 4; mt++)
#pragma unroll
        for (int nt = 0; nt < 4; nt++)
#pragma unroll
            for (int j = 0; j < 4; j++) acc[mt][nt][j] = 0.f;

    const int g  = lane >> 3, rr = lane & 7;
    const int lmo = ((g & 1) * 8 + rr) * 144 + (g >> 1) * 16;

    const __nv_bfloat16* gsrc[4] = {g_whi, g_wlo, g_mhi, g_mlo};

    auto ldchunk = [&](int ch, int st) {
#pragma unroll
        for (int a = 0; a < 4; a++) {
            const __nv_bfloat16* gp = gsrc[a];
            size_t rowbase = (a < 2) ? (size_t)(ob * 128) : (size_t)(pb * 128);
            char* dbase = dyn + ((a < 2) ? 0 : MBASE) + st * STGB + (a & 1) * SELB;
#pragma unroll
            for (int i = 0; i < 4; i++) {
                int idx = tid + i * 256;
                int r = idx >> 3, kc8 = (idx & 7) * 8;
                cp16(dbase + r * 144 + kc8 * 2,
                     gp + (rowbase + r) * 256 + ch * 64 + kc8);
            }
        }
    };

    ldchunk(0, 0);
    cp_commit();

#pragma unroll 1
    for (int ch = 0; ch < 4; ch++) {
        int st = ch & 1;
        if (ch < 3) {
            ldchunk(ch + 1, st ^ 1);
            cp_commit();
            cp_wait<1>();
        } else {
            cp_wait<0>();
        }
        __syncthreads();

        uint32_t wbase = uS + st * STGB + (wo * 64) * 144 + lmo;
        uint32_t bbase = uS + MBASE + st * STGB + (wp * 32) * 144 + lmo;

#pragma unroll
        for (int ks = 0; ks < 4; ks++) {
            int kb = ks * 32;
            uint32_t bh[8], bl[8];
            ldsm4(bh[0], bh[1], bh[2], bh[3], bbase + kb);
            ldsm4(bh[4], bh[5], bh[6], bh[7], bbase + 16 * 144 + kb);
            ldsm4(bl[0], bl[1], bl[2], bl[3], bbase + SELB + kb);
            ldsm4(bl[4], bl[5], bl[6], bl[7], bbase + SELB + 16 * 144 + kb);
#pragma unroll
            for (int mt = 0; mt < 4; mt++) {
                uint32_t ah[4], al[4];
                uint32_t abase = wbase + mt * 16 * 144 + kb;
                ldsm4(ah[0], ah[1], ah[2], ah[3], abase);
                ldsm4(al[0], al[1], al[2], al[3], abase + SELB);
#pragma unroll
                for (int nt = 0; nt < 4; nt++) {
                    uint32_t b0h = bh[(nt & 1) + (nt >> 1) * 4];
                    uint32_t b1h = bh[(nt & 1) + (nt >> 1) * 4 + 2];
                    uint32_t b0l = bl[(nt & 1) + (nt >> 1) * 4];
                    uint32_t b1l = bl[(nt & 1) + (nt >> 1) * 4 + 2];
                    mma_bf16(acc[mt][nt], ah, b0h, b1h);
                    mma_bf16(acc[mt][nt], ah, b0l, b1l);
                    mma_bf16(acc[mt][nt], al, b0h, b1h);
                }
            }
        }
        __syncthreads();
    }

    int pxg = pb * 128;
    int bidx = pxg >> 12;
    int hw0  = pxg & 4095;
    float* obase = out + (size_t)bidx * 1048576;
    int o_w  = ob * 128 + wo * 64;
    int px_w = hw0 + wp * 32;
#pragma unroll
    for (int mt = 0; mt < 4; mt++) {
        int r0 = o_w + mt * 16 + (lane >> 2);
        float bias0 = __ldg(g_bias + r0);
        float bias1 = __ldg(g_bias + r0 + 8);
        float* row0 = obase + (size_t)r0 * 4096;
        float* row1 = row0 + 8 * 4096;
#pragma unroll
        for (int nt = 0; nt < 4; nt++) {
            int px = px_w + nt * 8 + (lane & 3) * 2;
            float2 v0 = make_float2(fmaxf(acc[mt][nt][0] + bias0, 0.f),
                                    fmaxf(acc[mt][nt][1] + bias0, 0.f));
            float2 v1 = make_float2(fmaxf(acc[mt][nt][2] + bias1, 0.f),
                                    fmaxf(acc[mt][nt][3] + bias1, 0.f));
            *(float2*)(row0 + px) = v0;
            *(float2*)(row1 + px) = v1;
        }
    }
}

// ---------------- launch ----------------
extern "C" void kernel_launch(void* const* d_in, const int* in_sizes, int n_in,
                              void* d_out, int out_size) {
    const float* x    = (const float*)d_in[0];
    const float* gf   = (const float*)d_in[1];
    const float* offw = (const float*)d_in[2];
    const float* og   = (const float*)d_in[3];
    const float* obt  = (const float*)d_in[4];
    const float* om   = (const float*)d_in[5];
    const float* ov   = (const float*)d_in[6];
    const float* dww  = (const float*)d_in[7];
    const float* pww  = (const float*)d_in[8];
    const float* bg   = (const float*)d_in[9];
    const float* bb   = (const float*)d_in[10];
    const float* bm   = (const float*)d_in[11];
    const float* bv   = (const float*)d_in[12];
    float* out = (float*)d_out;

    cudaFuncSetAttribute(k_gemm_mma, cudaFuncAttributeMaxDynamicSharedMemorySize, 147456);

    k_transpose<<<dim3(128, 8, 4), dim3(32, 8)>>>(x);
    k_prep<<<256, 256>>>(pww, bg, bb, bm, bv);
    k_offset<<<256, 64>>>(gf, offw, og, obt, om, ov);
    k_sample<<<1024, 256>>>(dww);
    k_gemm_mma<<<dim3(128, 2), 256, 147456>>>(out);
}